// round 4
// baseline (speedup 1.0000x reference)
#include <cuda_runtime.h>
#include <stdint.h>

#define NN   50000
#define HID  128
#define NREL 3

// ---------------- scratch (device globals; 16B-aligned for float4 access) ---
__device__ __align__(16) float g_h  [(size_t)NN * HID];       // current features
__device__ __align__(16) float g_out[(size_t)NN * HID];       // layer accumulator
__device__ __align__(16) float g_hw [NREL][(size_t)NN * HID]; // h @ w[r]
__device__ __align__(16) float g_dis[NREL][NN];               // rsqrt(deg+1)
__device__ __align__(16) int   g_deg[NREL][NN];

// ---------------- degree / normalization ------------------------------------
__global__ void zero_deg_kernel() {
    int i = blockIdx.x * blockDim.x + threadIdx.x;
    if (i < NREL * NN) ((int*)g_deg)[i] = 0;
}

// edge_index is int32 (JAX default x64-disabled downgrades int64 -> int32).
__global__ void count_kernel(const int* __restrict__ edges, int E) {
    const int r = blockIdx.y;
    const int* dst = edges + (size_t)(2 * r + 1) * E;
    for (int e = blockIdx.x * blockDim.x + threadIdx.x; e < E;
         e += gridDim.x * blockDim.x) {
        int d = dst[e];
        if ((unsigned)d < NN) atomicAdd(&g_deg[r][d], 1);
    }
}

__global__ void dis_kernel() {
    int i = blockIdx.x * blockDim.x + threadIdx.x;
    if (i < NREL * NN) {
        int c = ((const int*)g_deg)[i];
        ((float*)g_dis)[i] = rsqrtf((float)c + 1.0f);
    }
}

// ---------------- register-tiled SGEMM --------------------------------------
// MODE 0: g_h   = relu(Aext @ B + bias)            (embedder, grid.y == 1)
// MODE 1: g_hw[r] = g_h @ B[r]                      (relation GEMMs, grid.y == 3)
// MODE 2: Cext  = g_h @ B + bias                    (final linear, grid.y == 1)
template <int BM, int BN, int BK, int TM, int TN, int MODE>
__launch_bounds__(256)
__global__ void sgemm_kernel(const float* __restrict__ Aext,
                             const float* __restrict__ Bmat,
                             const float* __restrict__ bias,
                             float* __restrict__ Cext,
                             int M, int K) {
    const int r = blockIdx.y;
    const float* A = (MODE == 0) ? Aext : g_h;
    const float* B = Bmat + (size_t)r * K * BN;

    __shared__ float As[BK][BM + 4];   // transposed A tile
    __shared__ float Bs[BK][BN];

    const int tid  = threadIdx.x;
    constexpr int TC = BN / TN;        // threads along N
    const int trow = tid / TC;
    const int tcol = tid % TC;
    const int rowBase = blockIdx.x * BM;

    float acc[TM][TN];
#pragma unroll
    for (int i = 0; i < TM; i++)
#pragma unroll
        for (int j = 0; j < TN; j++) acc[i][j] = 0.f;

    for (int k0 = 0; k0 < K; k0 += BK) {
        for (int i = tid; i < BM * BK; i += 256) {
            int rr = i / BK, cc = i % BK;
            int gr = rowBase + rr, gc = k0 + cc;
            As[cc][rr] = (gr < M && gc < K) ? A[(size_t)gr * K + gc] : 0.f;
        }
        for (int i = tid; i < BK * BN; i += 256) {
            int rr = i / BN, cc = i % BN;
            int gk = k0 + rr;
            Bs[rr][cc] = (gk < K) ? B[(size_t)gk * BN + cc] : 0.f;
        }
        __syncthreads();
#pragma unroll
        for (int kk = 0; kk < BK; kk++) {
            float a[TM], b[TN];
#pragma unroll
            for (int i = 0; i < TM; i++) a[i] = As[kk][trow * TM + i];
#pragma unroll
            for (int j = 0; j < TN; j++) b[j] = Bs[kk][tcol * TN + j];
#pragma unroll
            for (int i = 0; i < TM; i++)
#pragma unroll
                for (int j = 0; j < TN; j++)
                    acc[i][j] = fmaf(a[i], b[j], acc[i][j]);
        }
        __syncthreads();
    }

#pragma unroll
    for (int i = 0; i < TM; i++) {
        int gr = rowBase + trow * TM + i;
        if (gr >= M) continue;
#pragma unroll
        for (int j = 0; j < TN; j++) {
            int gc = tcol * TN + j;
            float v = acc[i][j];
            if (MODE == 0) {
                g_h[(size_t)gr * BN + gc] = fmaxf(v + bias[gc], 0.f);
            } else if (MODE == 1) {
                g_hw[r][(size_t)gr * BN + gc] = v;
            } else {
                Cext[(size_t)gr * BN + gc] = v + bias[gc];
            }
        }
    }
}

// ---------------- self-loop term + biases ------------------------------------
// out[i,c] = sum_r ( hw[r][i,c] * dis[r][i]^2 + b[r][c] )
__global__ void self_combine_kernel(const float* __restrict__ bias) {
    int idx = blockIdx.x * blockDim.x + threadIdx.x;  // over NN * 32 float4s
    const int total = NN * (HID / 4);
    if (idx >= total) return;
    int node = idx >> 5;
    int q    = idx & 31;
    float4 s = make_float4(0.f, 0.f, 0.f, 0.f);
#pragma unroll
    for (int r = 0; r < NREL; r++) {
        float dv = g_dis[r][node];
        dv *= dv;
        float4 hv = ((const float4*)g_hw[r])[idx];
        s.x += hv.x * dv + bias[r * HID + q * 4 + 0];
        s.y += hv.y * dv + bias[r * HID + q * 4 + 1];
        s.z += hv.z * dv + bias[r * HID + q * 4 + 2];
        s.w += hv.w * dv + bias[r * HID + q * 4 + 3];
    }
    ((float4*)g_out)[idx] = s;
}

// ---------------- edge scatter: warp per edge --------------------------------
__global__ void scatter_kernel(const int* __restrict__ edges, int E) {
    const int r = blockIdx.y;
    const int* __restrict__ src = edges + (size_t)(2 * r) * E;
    const int* __restrict__ dst = src + E;
    const float* dis = g_dis[r];
    const float* hw  = g_hw[r];

    const int lane   = threadIdx.x & 31;
    const int warp   = (blockIdx.x * blockDim.x + threadIdx.x) >> 5;
    const int nwarps = (gridDim.x * blockDim.x) >> 5;

    for (int e = warp; e < E; e += nwarps) {
        int s = src[e];
        int d = dst[e];
        if ((unsigned)s >= NN || (unsigned)d >= NN) continue;
        float c = dis[s] * dis[d];
        float4 v = ((const float4*)(hw + (size_t)s * HID))[lane];
        float* o = g_out + (size_t)d * HID + lane * 4;
        atomicAdd(o + 0, v.x * c);
        atomicAdd(o + 1, v.y * c);
        atomicAdd(o + 2, v.z * c);
        atomicAdd(o + 3, v.w * c);
    }
}

__global__ void relu_kernel() {
    int idx = blockIdx.x * blockDim.x + threadIdx.x;
    const int total = NN * (HID / 4);
    if (idx >= total) return;
    float4 v = ((const float4*)g_out)[idx];
    v.x = fmaxf(v.x, 0.f);
    v.y = fmaxf(v.y, 0.f);
    v.z = fmaxf(v.z, 0.f);
    v.w = fmaxf(v.w, 0.f);
    ((float4*)g_h)[idx] = v;
}

// ---------------- launch ------------------------------------------------------
extern "C" void kernel_launch(void* const* d_in, const int* in_sizes, int n_in,
                              void* d_out, int out_size) {
    const float* x     = (const float*)d_in[0];
    const int*   ei    = (const int*)d_in[1];   // int32! (JAX x64 disabled)
    const float* emb_w = (const float*)d_in[2];
    const float* emb_b = (const float*)d_in[3];
    const float* w0    = (const float*)d_in[4];
    const float* b0    = (const float*)d_in[5];
    const float* w1    = (const float*)d_in[6];
    const float* b1    = (const float*)d_in[7];
    const float* lin_w = (const float*)d_in[8];
    const float* lin_b = (const float*)d_in[9];
    float* out = (float*)d_out;

    const int E = in_sizes[1] / (2 * NREL);
    const int M = NN;

    // degree + normalization (shared by both layers)
    zero_deg_kernel<<<(NREL * NN + 255) / 256, 256>>>();
    count_kernel<<<dim3(256, NREL), 256>>>(ei, E);
    dis_kernel<<<(NREL * NN + 255) / 256, 256>>>();

    dim3 g1((M + 127) / 128, 1);
    dim3 g3((M + 127) / 128, NREL);
    const int elem_blocks = (NN * (HID / 4) + 255) / 256;

    // embedder: h = relu(x @ emb_w + emb_b)
    sgemm_kernel<128, 128, 16, 8, 8, 0><<<g1, 256>>>(x, emb_w, emb_b, nullptr, M, 300);

    // layer 0
    sgemm_kernel<128, 128, 16, 8, 8, 1><<<g3, 256>>>(nullptr, w0, nullptr, nullptr, M, HID);
    self_combine_kernel<<<elem_blocks, 256>>>(b0);
    scatter_kernel<<<dim3(1184, NREL), 256>>>(ei, E);
    relu_kernel<<<elem_blocks, 256>>>();

    // layer 1
    sgemm_kernel<128, 128, 16, 8, 8, 1><<<g3, 256>>>(nullptr, w1, nullptr, nullptr, M, HID);
    self_combine_kernel<<<elem_blocks, 256>>>(b1);
    scatter_kernel<<<dim3(1184, NREL), 256>>>(ei, E);
    relu_kernel<<<elem_blocks, 256>>>();

    // final linear: out = h @ lin_w + lin_b
    sgemm_kernel<128, 64, 16, 8, 4, 2><<<g1, 256>>>(nullptr, lin_w, lin_b, out, M, HID);
}

// round 5
// speedup vs baseline: 2.5985x; 2.5985x over previous
#include <cuda_runtime.h>
#include <stdint.h>

#define NN    50000
#define HID   128
#define NREL  3
#define EMAX  800000

// ---------------- scratch (device globals; 16B-aligned) ----------------------
__device__ __align__(16) float g_h  [(size_t)NN * HID];        // current features
__device__ __align__(16) float g_hw [NREL][(size_t)NN * HID];  // (h @ w[r]) * dis[r]
__device__ __align__(16) float g_dis[NREL][NN];                // rsqrt(deg+1)
__device__ __align__(16) int   g_deg[NREL][NN];
__device__ __align__(16) int   g_off[NREL][NN + 1];            // CSR row offsets
__device__ __align__(16) int   g_cur[NREL][NN];                // fill cursors
__device__ __align__(16) int   g_csr[NREL][EMAX];              // src sorted by dst

// ---------------- degree ------------------------------------------------------
__global__ void zero_deg_kernel() {
    int i = blockIdx.x * blockDim.x + threadIdx.x;
    if (i < NREL * NN) ((int*)g_deg)[i] = 0;
}

__global__ void count_kernel(const int* __restrict__ edges, int E) {
    const int r = blockIdx.y;
    const int* dst = edges + (size_t)(2 * r + 1) * E;
    for (int e = blockIdx.x * blockDim.x + threadIdx.x; e < E;
         e += gridDim.x * blockDim.x) {
        int d = dst[e];
        if ((unsigned)d < NN) atomicAdd(&g_deg[r][d], 1);
    }
}

// ---------------- block-sequential exclusive scan (one block per relation) ---
__global__ __launch_bounds__(1024) void scan_kernel() {
    const int r = blockIdx.x;
    __shared__ int warp_sums[32];
    __shared__ int s_carry;
    if (threadIdx.x == 0) s_carry = 0;
    __syncthreads();
    const int lane = threadIdx.x & 31;
    const int wid  = threadIdx.x >> 5;
    for (int base = 0; base < NN; base += 1024) {
        int i = base + (int)threadIdx.x;
        int v = (i < NN) ? g_deg[r][i] : 0;
        // warp inclusive scan
        int x = v;
#pragma unroll
        for (int o = 1; o < 32; o <<= 1) {
            int y = __shfl_up_sync(0xffffffffu, x, o);
            if (lane >= o) x += y;
        }
        if (lane == 31) warp_sums[wid] = x;
        __syncthreads();
        if (threadIdx.x < 32) {
            int w = warp_sums[threadIdx.x];
#pragma unroll
            for (int o = 1; o < 32; o <<= 1) {
                int y = __shfl_up_sync(0xffffffffu, w, o);
                if ((int)threadIdx.x >= o) w += y;
            }
            warp_sums[threadIdx.x] = w;
        }
        __syncthreads();
        int incl = x + (wid > 0 ? warp_sums[wid - 1] : 0);
        int excl = incl - v + s_carry;
        if (i < NN) { g_off[r][i] = excl; g_cur[r][i] = excl; }
        int block_total = warp_sums[31];
        __syncthreads();
        if (threadIdx.x == 0) s_carry += block_total;
        __syncthreads();
    }
    if (threadIdx.x == 0) g_off[r][NN] = s_carry;
}

__global__ void dis_kernel() {
    int i = blockIdx.x * blockDim.x + threadIdx.x;
    if (i < NREL * NN) {
        int c = ((const int*)g_deg)[i];
        ((float*)g_dis)[i] = rsqrtf((float)c + 1.0f);
    }
}

__global__ void fill_csr_kernel(const int* __restrict__ edges, int E) {
    const int r = blockIdx.y;
    const int* src = edges + (size_t)(2 * r) * E;
    const int* dst = src + E;
    for (int e = blockIdx.x * blockDim.x + threadIdx.x; e < E;
         e += gridDim.x * blockDim.x) {
        int s = src[e], d = dst[e];
        if ((unsigned)d < NN && (unsigned)s < NN) {
            int pos = atomicAdd(&g_cur[r][d], 1);
            g_csr[r][pos] = s;
        }
    }
}

// ---------------- register-tiled SGEMM with reg-prefetch pipelining ----------
// MODE 0: g_h    = relu(Aext @ B + bias)                (embedder, scalar loads)
// MODE 1: g_hw[r]= (g_h @ B[r]) * dis[r][row]           (relation GEMMs, float4)
// MODE 2: Cext   = g_h @ B + bias                       (final linear, float4)
template <int BM, int BN, int BK, int TM, int TN, int MODE>
__launch_bounds__(256)
__global__ void sgemm_kernel(const float* __restrict__ Aext,
                             const float* __restrict__ Bmat,
                             const float* __restrict__ bias,
                             float* __restrict__ Cext,
                             int M, int K) {
    constexpr bool VEC = (MODE != 0);   // K==128 paths, 16B-aligned
    const int r = blockIdx.y;
    const float* A = (MODE == 0) ? Aext : g_h;
    const float* B = Bmat + (size_t)r * K * BN;

    __shared__ float As[BK][BM + 4];
    __shared__ float Bs[BK][BN];

    const int tid  = threadIdx.x;
    constexpr int TC = BN / TN;
    const int trow = tid / TC;
    const int tcol = tid % TC;
    const int rowBase = blockIdx.x * BM;

    float acc[TM][TN];
#pragma unroll
    for (int i = 0; i < TM; i++)
#pragma unroll
        for (int j = 0; j < TN; j++) acc[i][j] = 0.f;

    const int ntiles = (K + BK - 1) / BK;

    // prefetch registers
    constexpr int AF4 = VEC ? (BM * BK) / (4 * 256) : 1;
    constexpr int BF4 = VEC ? (BK * BN) / (4 * 256) : 1;
    constexpr int ASC = VEC ? 1 : (BM * BK) / 256;
    constexpr int BSC = VEC ? 1 : (BK * BN) / 256;
    float4 va[AF4], vb[BF4];
    float  sa[ASC], sb[BSC];

    // ---- tile loaders ----
    auto fetch = [&](int k0) {
        if (VEC) {
#pragma unroll
            for (int v = 0; v < AF4; v++) {
                int g   = tid + v * 256;
                int row = g / (BK / 4);
                int c4  = g % (BK / 4);
                int gr  = rowBase + row; if (gr >= M) gr = M - 1;
                va[v] = *(const float4*)&A[(size_t)gr * K + k0 + c4 * 4];
            }
#pragma unroll
            for (int v = 0; v < BF4; v++) {
                int g   = tid + v * 256;
                int row = g / (BN / 4);
                int c4  = g % (BN / 4);
                vb[v] = *(const float4*)&B[(size_t)(k0 + row) * BN + c4 * 4];
            }
        } else {
#pragma unroll
            for (int v = 0; v < ASC; v++) {
                int g  = tid + v * 256;
                int rr = g / BK, cc = g % BK;
                int gr = rowBase + rr; if (gr >= M) gr = M - 1;
                int gc = k0 + cc;
                sa[v] = (gc < K) ? A[(size_t)gr * K + gc] : 0.f;
            }
#pragma unroll
            for (int v = 0; v < BSC; v++) {
                int g  = tid + v * 256;
                int rr = g / BN, cc = g % BN;
                int gk = k0 + rr;
                sb[v] = (gk < K) ? B[(size_t)gk * BN + cc] : 0.f;
            }
        }
    };
    auto commit = [&]() {
        if (VEC) {
#pragma unroll
            for (int v = 0; v < AF4; v++) {
                int g   = tid + v * 256;
                int row = g / (BK / 4);
                int c4  = g % (BK / 4);
                As[c4 * 4 + 0][row] = va[v].x;
                As[c4 * 4 + 1][row] = va[v].y;
                As[c4 * 4 + 2][row] = va[v].z;
                As[c4 * 4 + 3][row] = va[v].w;
            }
#pragma unroll
            for (int v = 0; v < BF4; v++) {
                int g   = tid + v * 256;
                int row = g / (BN / 4);
                int c4  = g % (BN / 4);
                *(float4*)&Bs[row][c4 * 4] = vb[v];
            }
        } else {
#pragma unroll
            for (int v = 0; v < ASC; v++) {
                int g  = tid + v * 256;
                As[g % BK][g / BK] = sa[v];
            }
#pragma unroll
            for (int v = 0; v < BSC; v++) {
                int g  = tid + v * 256;
                Bs[g / BN][g % BN] = sb[v];
            }
        }
    };

    fetch(0);
    commit();
    __syncthreads();

    for (int t = 0; t < ntiles; t++) {
        if (t + 1 < ntiles) fetch((t + 1) * BK);
#pragma unroll
        for (int kk = 0; kk < BK; kk++) {
            float a[TM], b[TN];
#pragma unroll
            for (int i = 0; i < TM; i++) a[i] = As[kk][trow * TM + i];
#pragma unroll
            for (int j = 0; j < TN; j++) b[j] = Bs[kk][tcol * TN + j];
#pragma unroll
            for (int i = 0; i < TM; i++)
#pragma unroll
                for (int j = 0; j < TN; j++)
                    acc[i][j] = fmaf(a[i], b[j], acc[i][j]);
        }
        __syncthreads();
        if (t + 1 < ntiles) {
            commit();
            __syncthreads();
        }
    }

#pragma unroll
    for (int i = 0; i < TM; i++) {
        int gr = rowBase + trow * TM + i;
        if (gr >= M) continue;
        float dscale = (MODE == 1) ? g_dis[r][gr] : 1.f;
#pragma unroll
        for (int j = 0; j < TN; j++) {
            int gc = tcol * TN + j;
            float v = acc[i][j];
            if (MODE == 0) {
                g_h[(size_t)gr * BN + gc] = fmaxf(v + bias[gc], 0.f);
            } else if (MODE == 1) {
                g_hw[r][(size_t)gr * BN + gc] = v * dscale;
            } else {
                Cext[(size_t)gr * BN + gc] = v + bias[gc];
            }
        }
    }
}

// ---------------- CSR gather: warp per node, fused self+bias+relu ------------
// g_h[d] = relu( sum_r dis_r[d] * ( hws_r[d] + sum_{s in N_r(d)} hws_r[s] ) + sum_r b_r )
__launch_bounds__(256)
__global__ void gather_kernel(const float* __restrict__ bias) {
    const int node = (blockIdx.x * blockDim.x + threadIdx.x) >> 5;
    const int lane = threadIdx.x & 31;
    if (node >= NN) return;
    const int c0 = lane * 4;

    float4 tot;
    tot.x = bias[c0 + 0] + bias[HID + c0 + 0] + bias[2 * HID + c0 + 0];
    tot.y = bias[c0 + 1] + bias[HID + c0 + 1] + bias[2 * HID + c0 + 1];
    tot.z = bias[c0 + 2] + bias[HID + c0 + 2] + bias[2 * HID + c0 + 2];
    tot.w = bias[c0 + 3] + bias[HID + c0 + 3] + bias[2 * HID + c0 + 3];

#pragma unroll
    for (int r = 0; r < NREL; r++) {
        const float4* hw4 = (const float4*)g_hw[r];
        float4 a = hw4[(size_t)node * (HID / 4) + lane];   // self loop (pre-scaled)
        const int beg = g_off[r][node];
        const int end = g_off[r][node + 1];
        const int* __restrict__ csr = g_csr[r];
        for (int t = beg; t < end; t += 32) {
            int idx = (t + lane < end) ? csr[t + lane] : 0;
            int n = end - t; if (n > 32) n = 32;
            for (int j = 0; j < n; j++) {
                int s = __shfl_sync(0xffffffffu, idx, j);
                float4 v = hw4[(size_t)s * (HID / 4) + lane];
                a.x += v.x; a.y += v.y; a.z += v.z; a.w += v.w;
            }
        }
        float dd = g_dis[r][node];
        tot.x += a.x * dd; tot.y += a.y * dd;
        tot.z += a.z * dd; tot.w += a.w * dd;
    }
    tot.x = fmaxf(tot.x, 0.f);
    tot.y = fmaxf(tot.y, 0.f);
    tot.z = fmaxf(tot.z, 0.f);
    tot.w = fmaxf(tot.w, 0.f);
    ((float4*)g_h)[(size_t)node * (HID / 4) + lane] = tot;
}

// ---------------- launch ------------------------------------------------------
extern "C" void kernel_launch(void* const* d_in, const int* in_sizes, int n_in,
                              void* d_out, int out_size) {
    const float* x     = (const float*)d_in[0];
    const int*   ei    = (const int*)d_in[1];   // int32 (JAX x64 disabled)
    const float* emb_w = (const float*)d_in[2];
    const float* emb_b = (const float*)d_in[3];
    const float* w0    = (const float*)d_in[4];
    const float* b0    = (const float*)d_in[5];
    const float* w1    = (const float*)d_in[6];
    const float* b1    = (const float*)d_in[7];
    const float* lin_w = (const float*)d_in[8];
    const float* lin_b = (const float*)d_in[9];
    float* out = (float*)d_out;

    const int E = in_sizes[1] / (2 * NREL);
    const int M = NN;

    // CSR build (shared by both layers)
    zero_deg_kernel<<<(NREL * NN + 255) / 256, 256>>>();
    count_kernel<<<dim3(256, NREL), 256>>>(ei, E);
    scan_kernel<<<NREL, 1024>>>();
    dis_kernel<<<(NREL * NN + 255) / 256, 256>>>();
    fill_csr_kernel<<<dim3(256, NREL), 256>>>(ei, E);

    const int gather_blocks = (NN * 32 + 255) / 256;   // warp per node

    // embedder: h = relu(x @ emb_w + emb_b)
    sgemm_kernel<64, 128, 16, 4, 8, 0>
        <<<dim3((M + 63) / 64, 1), 256>>>(x, emb_w, emb_b, nullptr, M, 300);

    // layer 0
    sgemm_kernel<128, 128, 16, 8, 8, 1>
        <<<dim3((M + 127) / 128, NREL), 256>>>(nullptr, w0, nullptr, nullptr, M, HID);
    gather_kernel<<<gather_blocks, 256>>>(b0);

    // layer 1
    sgemm_kernel<128, 128, 16, 8, 8, 1>
        <<<dim3((M + 127) / 128, NREL), 256>>>(nullptr, w1, nullptr, nullptr, M, HID);
    gather_kernel<<<gather_blocks, 256>>>(b1);

    // final linear: out = h @ lin_w + lin_b
    sgemm_kernel<128, 64, 16, 8, 4, 2>
        <<<dim3((M + 127) / 128, 1), 256>>>(nullptr, lin_w, lin_b, out, M, HID);
}